// round 6
// baseline (speedup 1.0000x reference)
#include <cuda_runtime.h>

#define HH 224
#define WW 224
#define HW (HH * WW)
#define BB 256
#define NTOT (BB * HW)
#define DTc 0.15f
#define PIf 3.14159265358979f

#define TY 46                  // interior rows per tile
#define HALO 5                 // 5 fused steps per kernel
#define RR (TY + 2 * HALO)     // 56 data rows in tile
#define RPAIRS (RR / 2)        // 28 data row-pairs (packs)
#define RPP (RPAIRS + 2)       // +2 zero-pad pack rows -> 30
#define PWP 232                // padded row stride in cells (29 x 128B)
#define XOFF 8                 // first data cell (lane0 of warp0 -> 128B aligned)
#define TILES 5                // 5*46 = 230 >= 224
#define NTHREADS 896           // 4 strips x 224 columns
#define STRIPS 4
#define PACKS_PER (RPAIRS / STRIPS)  // 7 packs per thread
#define SMP (RPP * PWP)        // ulonglong2 cells per buffer (6960)
#define SMEM_BYTES (2 * SMP * 16)    // 222720 B

typedef unsigned long long u64;

// Intermediate state between the two fused kernels (no allocs allowed).
__device__ float g_s[NTOT];
__device__ float g_c[NTOT];

// ---- packed f32x2 helpers ----
__device__ __forceinline__ u64 pk2(float lo, float hi) {
    u64 r; asm("mov.b64 %0, {%1, %2};" : "=l"(r) : "f"(lo), "f"(hi)); return r;
}
__device__ __forceinline__ void unpk2(u64 v, float& lo, float& hi) {
    asm("mov.b64 {%0, %1}, %2;" : "=f"(lo), "=f"(hi) : "l"(v));
}
// (a.hi, b.lo)
__device__ __forceinline__ u64 funnel(u64 a, u64 b) {
    u64 r;
    asm("{\n\t.reg .f32 al, ah, bl, bh;\n\t"
        "mov.b64 {al, ah}, %1;\n\t"
        "mov.b64 {bl, bh}, %2;\n\t"
        "mov.b64 %0, {ah, bl};\n\t}"
        : "=l"(r) : "l"(a), "l"(b));
    return r;
}
__device__ __forceinline__ u64 add2(u64 a, u64 b) {
    u64 d; asm("add.rn.f32x2 %0, %1, %2;" : "=l"(d) : "l"(a), "l"(b)); return d;
}
__device__ __forceinline__ u64 mul2(u64 a, u64 b) {
    u64 d; asm("mul.rn.f32x2 %0, %1, %2;" : "=l"(d) : "l"(a), "l"(b)); return d;
}
__device__ __forceinline__ u64 fma2(u64 a, u64 b, u64 c) {
    u64 d; asm("fma.rn.f32x2 %0, %1, %2, %3;" : "=l"(d) : "l"(a), "l"(b), "l"(c)); return d;
}
__device__ __forceinline__ u64 neg2(u64 a) { return a ^ 0x8000000080000000ULL; }

// Predicated single-lane LDS.128 patch: on lanes where pred != 0, overwrite v
// with the 16B cell at shared address addr. No branch, no BSSY.
__device__ __forceinline__ void patch_lds(ulonglong2& v, unsigned addr, int pred) {
    asm volatile(
        "{\n\t.reg .pred pp;\n\t"
        "setp.ne.u32 pp, %2, 0;\n\t"
        "@pp ld.shared.v2.u64 {%0, %1}, [%3];\n\t}"
        : "+l"(v.x), "+l"(v.y)
        : "r"(pred), "r"(addr));
}

template <int PHASE>  // 0: init from x_img -> g_s/g_c ; 1: g_s/g_c -> out
__global__ void __launch_bounds__(NTHREADS, 1)
fused5_kernel(const float* __restrict__ x_img,
              const float* __restrict__ omega,
              const float* __restrict__ Kp,
              float* __restrict__ out) {
    extern __shared__ ulonglong2 sm2[];
    ulonglong2* bufA = sm2;
    ulonglong2* bufB = sm2 + SMP;
    const unsigned baseA_u32 = (unsigned)__cvta_generic_to_shared(bufA);
    const unsigned baseB_u32 = (unsigned)__cvta_generic_to_shared(bufB);

    const int tid = threadIdx.x;
    const int x = tid % WW;            // column 0..223; warps = 32 consecutive cols
    const int lane = tid & 31;
    const int strip = tid / WW;        // 0..3
    const int r0p = 1 + strip * PACKS_PER;
    const int xc = x + XOFF;
    const int b = blockIdx.y;
    const int y0 = blockIdx.x * TY;
    const float DTK = DTc * Kp[0];
    const u64 DTK2 = pk2(DTK, DTK);
    const u64 ONE2 = pk2(1.0f, 1.0f);
    const u64 C3 = pk2(-1.0f / 6.0f, -1.0f / 6.0f);
    const u64 C5 = pk2(8.3333333e-3f, 8.3333333e-3f);
    const u64 C2 = pk2(-0.5f, -0.5f);
    const u64 C4 = pk2(4.1666668e-2f, 4.1666668e-2f);

    // Zero the pad ring of both buffers: full top/bottom pack rows + the
    // XOFF-cell left pad of every row (which also serves as the "right pad"
    // of the previous row, since stride wraps x=223's right neighbor there).
    const ulonglong2 Z = make_ulonglong2(0ULL, 0ULL);
    for (int i = tid; i < PWP; i += NTHREADS) {
        bufA[i] = Z; bufA[(RPP - 1) * PWP + i] = Z;
        bufB[i] = Z; bufB[(RPP - 1) * PWP + i] = Z;
    }
    for (int k = tid; k < (RPP - 2) * XOFF; k += NTHREADS) {
        int r = 1 + k / XOFF;
        int cix = k % XOFF;
        bufA[r * PWP + cix] = Z;
        bufB[r * PWP + cix] = Z;
    }

    // Per-pack DT*omega (0 outside image) + load initial state into bufA
    // (unconditional store: out-of-image rows get exact zeros).
    u64 dto2[PACKS_PER];
#pragma unroll
    for (int j = 0; j < PACKS_PER; j++) {
        const int rp = r0p + j;
        const int rt0 = 2 * (rp - 1);          // tile row of lo element
        const int gy0 = y0 - HALO + rt0;
        const int gy1 = gy0 + 1;
        const bool in0 = (gy0 >= 0) && (gy0 < HH);
        const bool in1 = (gy1 >= 0) && (gy1 < HH);
        float o0 = in0 ? DTc * omega[gy0 * WW + x] : 0.0f;
        float o1 = in1 ? DTc * omega[gy1 * WW + x] : 0.0f;
        dto2[j] = pk2(o0, o1);

        float s0 = 0.0f, c0 = 0.0f, s1 = 0.0f, c1 = 0.0f;
        if (PHASE == 0) {
            // theta0 = pi*(2x-1) in [-pi, pi]: hardware sincos is plenty accurate.
            if (in0) __sincosf(fmaf(2.0f * PIf, x_img[b * HW + gy0 * WW + x], -PIf), &s0, &c0);
            if (in1) __sincosf(fmaf(2.0f * PIf, x_img[b * HW + gy1 * WW + x], -PIf), &s1, &c1);
        } else {
            if (in0) { s0 = g_s[b * HW + gy0 * WW + x]; c0 = g_c[b * HW + gy0 * WW + x]; }
            if (in1) { s1 = g_s[b * HW + gy1 * WW + x]; c1 = g_c[b * HW + gy1 * WW + x]; }
        }
        bufA[rp * PWP + xc] = make_ulonglong2(pk2(s0, s1), pk2(c0, c1));
    }
    __syncthreads();

    // 5 fused steps, ping-pong A<->B.
    const ulonglong2* p = bufA;
    ulonglong2* q = bufB;
    unsigned p_u32 = baseA_u32;
#pragma unroll
    for (int st = 0; st < HALO; st++) {
        int idx = r0p * PWP + xc;
        ulonglong2 prev = p[idx - PWP];
        ulonglong2 cur = p[idx];
        // Carried partial vertical sums: u = prev + cur (per field).
        u64 u_s = add2(prev.x, cur.x);
        u64 u_c = add2(prev.y, cur.y);
#pragma unroll
        for (int j = 0; j < PACKS_PER; j++) {
            ulonglong2 nxt = p[idx + PWP];   // aligned LDS.128

            // Horizontal neighbors from lane registers; warp-edge lanes patch
            // from smem with a predicated 1-lane LDS (left pad cells are zero,
            // and x=223's right neighbor wraps to next row's zero pad).
            ulonglong2 lft, rgt;
            lft.x = __shfl_up_sync(0xffffffffu, cur.x, 1);
            lft.y = __shfl_up_sync(0xffffffffu, cur.y, 1);
            rgt.x = __shfl_down_sync(0xffffffffu, cur.x, 1);
            rgt.y = __shfl_down_sync(0xffffffffu, cur.y, 1);
            patch_lds(lft, p_u32 + (unsigned)(idx - 1) * 16u, lane == 0);
            patch_lds(rgt, p_u32 + (unsigned)(idx + 1) * 16u, lane == 31);

            u64 v_s = add2(cur.x, nxt.x);
            u64 v_c = add2(cur.y, nxt.y);
            // up+down neighbor sum = (u.hi, v.lo)
            u64 sn = add2(funnel(u_s, v_s), add2(lft.x, rgt.x));
            u64 cn = add2(funnel(u_c, v_c), add2(lft.y, rgt.y));

            // coupling = cos*sn - sin*cn  (m = -sin, reused below)
            u64 m = neg2(cur.x);
            u64 coup = fma2(cur.y, sn, mul2(m, cn));
            u64 d = fma2(DTK2, coup, dto2[j]);

            // |d| <= 0.3: Taylor sin/cos, err ~4e-8
            u64 d2 = mul2(d, d);
            u64 sd = mul2(d, fma2(d2, fma2(d2, C5, C3), ONE2));
            u64 cd = fma2(d2, fma2(d2, C4, C2), ONE2);

            u64 ns = fma2(cur.x, cd, mul2(cur.y, sd));
            u64 nc = fma2(cur.y, cd, mul2(m, sd));
            q[idx] = make_ulonglong2(ns, nc);  // aligned STS.128

            u_s = v_s; u_c = v_c;
            cur = nxt;
            idx += PWP;
        }
        __syncthreads();
        const ulonglong2* t = q;
        q = (ulonglong2*)p;
        p = t;
        p_u32 = (st & 1) ? baseA_u32 : baseB_u32;  // p after swap: st=0 -> B, st=1 -> A, ...
    }
    // Result now in p.

    // Write back interior rows (tile rows HALO..HALO+TY-1).
#pragma unroll
    for (int j = 0; j < PACKS_PER; j++) {
        const int rp = r0p + j;
        ulonglong2 v = p[rp * PWP + xc];
        float s0, s1, c0, c1;
        unpk2(v.x, s0, s1);
        unpk2(v.y, c0, c1);
        const int rt0 = 2 * (rp - 1);
#pragma unroll
        for (int par = 0; par < 2; par++) {
            const int rt = rt0 + par;
            if (rt >= HALO && rt < HALO + TY) {
                const int gy = y0 + (rt - HALO);
                if (gy < HH) {
                    const float s = par ? s1 : s0;
                    const float c = par ? c1 : c0;
                    if (PHASE == 0) {
                        const int gi = b * HW + gy * WW + x;
                        g_s[gi] = s;
                        g_c[gi] = c;
                    } else {
                        const int pix = gy * WW + x;
                        out[(long)b * (2 * HW) + pix] = c;       // cos channel
                        out[(long)b * (2 * HW) + HW + pix] = s;  // sin channel
                    }
                }
            }
        }
    }
}

extern "C" void kernel_launch(void* const* d_in, const int* in_sizes, int n_in,
                              void* d_out, int out_size) {
    const float* x_img = (const float*)d_in[0];  // (B,1,H,W)
    const float* omega = (const float*)d_in[1];  // (1,1,H,W)
    const float* Kp    = (const float*)d_in[2];  // scalar
    float* out = (float*)d_out;

    static bool configured = false;
    if (!configured) {
        cudaFuncSetAttribute(fused5_kernel<0>,
                             cudaFuncAttributeMaxDynamicSharedMemorySize, SMEM_BYTES);
        cudaFuncSetAttribute(fused5_kernel<1>,
                             cudaFuncAttributeMaxDynamicSharedMemorySize, SMEM_BYTES);
        configured = true;
    }

    dim3 grid(TILES, BB);
    dim3 block(NTHREADS);
    fused5_kernel<0><<<grid, block, SMEM_BYTES>>>(x_img, omega, Kp, out);
    fused5_kernel<1><<<grid, block, SMEM_BYTES>>>(x_img, omega, Kp, out);
}

// round 7
// speedup vs baseline: 1.1724x; 1.1724x over previous
#include <cuda_runtime.h>

#define HH 224
#define WW 224
#define HW (HH * WW)
#define BB 256
#define NTOT (BB * HW)
#define DTc 0.15f
#define PIf 3.14159265358979f

#define TY 46                  // interior rows per tile
#define HALO 5                 // 5 fused steps per kernel
#define RR (TY + 2 * HALO)     // 56 data rows in tile
#define RPAIRS (RR / 2)        // 28 vertical row-pair packs
#define RPP (RPAIRS + 2)       // +2 zero-pad pack rows -> 30
#define TCOLS 112              // thread-columns (each owns 2 pixel cols)
#define PW2 114                // plane width incl pads
#define RS (2 * PW2)           // row stride: E plane then O plane (228 cells)
#define TILES 5                // 5*46 = 230 >= 224
#define STRIPS 4
#define NTHREADS (TCOLS * STRIPS)    // 448 -> reg budget 146/thread
#define PACKS_PER (RPAIRS / STRIPS)  // 7
#define SMP (RPP * RS)               // cells per buffer = 6840
#define SMEM_BYTES (2 * SMP * 16)    // 218880 B

typedef unsigned long long u64;

// Intermediate state between the two fused kernels (no allocs allowed).
__device__ float g_s[NTOT];
__device__ float g_c[NTOT];

// ---- packed f32x2 helpers ----
__device__ __forceinline__ u64 pk2(float lo, float hi) {
    u64 r; asm("mov.b64 %0, {%1, %2};" : "=l"(r) : "f"(lo), "f"(hi)); return r;
}
__device__ __forceinline__ void unpk2(u64 v, float& lo, float& hi) {
    asm("mov.b64 {%0, %1}, %2;" : "=f"(lo), "=f"(hi) : "l"(v));
}
// (a.hi, b.lo)
__device__ __forceinline__ u64 funnel(u64 a, u64 b) {
    u64 r;
    asm("{\n\t.reg .f32 al, ah, bl, bh;\n\t"
        "mov.b64 {al, ah}, %1;\n\t"
        "mov.b64 {bl, bh}, %2;\n\t"
        "mov.b64 %0, {ah, bl};\n\t}"
        : "=l"(r) : "l"(a), "l"(b));
    return r;
}
__device__ __forceinline__ u64 add2(u64 a, u64 b) {
    u64 d; asm("add.rn.f32x2 %0, %1, %2;" : "=l"(d) : "l"(a), "l"(b)); return d;
}
__device__ __forceinline__ u64 mul2(u64 a, u64 b) {
    u64 d; asm("mul.rn.f32x2 %0, %1, %2;" : "=l"(d) : "l"(a), "l"(b)); return d;
}
__device__ __forceinline__ u64 fma2(u64 a, u64 b, u64 c) {
    u64 d; asm("fma.rn.f32x2 %0, %1, %2, %3;" : "=l"(d) : "l"(a), "l"(b), "l"(c)); return d;
}
__device__ __forceinline__ u64 neg2(u64 a) { return a ^ 0x8000000080000000ULL; }

struct SC { u64 DTK2, ONE2, C3, C5, C2, C4; };

// Rotation update for one pack given: carried vertical partial sum u (=prev+cur),
// fresh v (=cur+nxt), horizontal neighbor packs hl, hr.
__device__ __forceinline__ ulonglong2 upd(ulonglong2 cur, u64 u_s, u64 u_c,
                                          u64 v_s, u64 v_c,
                                          ulonglong2 hl, ulonglong2 hr,
                                          u64 dto, const SC& C) {
    u64 sn = add2(funnel(u_s, v_s), add2(hl.x, hr.x));
    u64 cn = add2(funnel(u_c, v_c), add2(hl.y, hr.y));
    u64 m = neg2(cur.x);
    u64 coup = fma2(cur.y, sn, mul2(m, cn));
    u64 d = fma2(C.DTK2, coup, dto);
    u64 d2 = mul2(d, d);
    u64 sd = mul2(d, fma2(d2, fma2(d2, C.C5, C.C3), C.ONE2));
    u64 cd = fma2(d2, fma2(d2, C.C4, C.C2), C.ONE2);
    ulonglong2 r;
    r.x = fma2(cur.x, cd, mul2(cur.y, sd));
    r.y = fma2(cur.y, cd, mul2(m, sd));
    return r;
}

template <int PHASE>  // 0: init from x_img -> g_s/g_c ; 1: g_s/g_c -> out
__global__ void __launch_bounds__(NTHREADS, 1)
fused5_kernel(const float* __restrict__ x_img,
              const float* __restrict__ omega,
              const float* __restrict__ Kp,
              float* __restrict__ out) {
    extern __shared__ ulonglong2 sm2[];
    ulonglong2* bufA = sm2;
    ulonglong2* bufB = sm2 + SMP;

    const int tid = threadIdx.x;
    const int t = tid % TCOLS;         // thread-column 0..111 (owns pixel cols 2t, 2t+1)
    const int strip = tid / TCOLS;     // 0..3
    const int r0p = 1 + strip * PACKS_PER;
    const int b = blockIdx.y;
    const int y0 = blockIdx.x * TY;
    const int xe = 2 * t;

    const float DTK = DTc * Kp[0];
    SC C;
    C.DTK2 = pk2(DTK, DTK);
    C.ONE2 = pk2(1.0f, 1.0f);
    C.C3 = pk2(-1.0f / 6.0f, -1.0f / 6.0f);
    C.C5 = pk2(8.3333333e-3f, 8.3333333e-3f);
    C.C2 = pk2(-0.5f, -0.5f);
    C.C4 = pk2(4.1666668e-2f, 4.1666668e-2f);

    // Plane cell indices. E-plane data cols 1..112 (pixel col 2(j-1)),
    // O-plane data cols 1..112 (pixel col 2j-1).
    const int iE = t + 1;              // own even col 2t
    const int iO = PW2 + t + 1;        // own odd col 2t+1
    const int iL = PW2 + t;            // left neighbor col 2t-1 (t=0 -> pad)
    const int iR = t + 2;              // right neighbor col 2t+2 (t=111 -> pad)

    // Zero pad ring only: full top/bottom pack rows + per-row pads
    // (E col 113 cell r*RS+113, O col 0 cell r*RS+114).
    const ulonglong2 Z = make_ulonglong2(0ULL, 0ULL);
    for (int i = tid; i < RS; i += NTHREADS) {
        bufA[i] = Z; bufA[(RPP - 1) * RS + i] = Z;
        bufB[i] = Z; bufB[(RPP - 1) * RS + i] = Z;
    }
    for (int r = 1 + tid; r < RPP - 1; r += NTHREADS) {
        bufA[r * RS + 113] = Z; bufA[r * RS + 114] = Z;
        bufB[r * RS + 113] = Z; bufB[r * RS + 114] = Z;
    }

    // Init: per-pack DT*omega for both owned cols + state into bufA
    // (unconditional store: out-of-image rows get exact zeros).
    u64 dtoE[PACKS_PER], dtoO[PACKS_PER];
#pragma unroll
    for (int j = 0; j < PACKS_PER; j++) {
        const int rp = r0p + j;
        const int rt0 = 2 * (rp - 1);
        const int gy0 = y0 - HALO + rt0;
        const int gy1 = gy0 + 1;
        const bool in0 = (gy0 >= 0) && (gy0 < HH);
        const bool in1 = (gy1 >= 0) && (gy1 < HH);

        float2 o0 = in0 ? *(const float2*)&omega[gy0 * WW + xe] : make_float2(0.f, 0.f);
        float2 o1 = in1 ? *(const float2*)&omega[gy1 * WW + xe] : make_float2(0.f, 0.f);
        dtoE[j] = pk2(DTc * o0.x, DTc * o1.x);
        dtoO[j] = pk2(DTc * o0.y, DTc * o1.y);

        float sE0 = 0.f, cE0 = 0.f, sO0 = 0.f, cO0 = 0.f;
        float sE1 = 0.f, cE1 = 0.f, sO1 = 0.f, cO1 = 0.f;
        if (PHASE == 0) {
            if (in0) {
                float2 v = *(const float2*)&x_img[b * HW + gy0 * WW + xe];
                __sincosf(fmaf(2.0f * PIf, v.x, -PIf), &sE0, &cE0);
                __sincosf(fmaf(2.0f * PIf, v.y, -PIf), &sO0, &cO0);
            }
            if (in1) {
                float2 v = *(const float2*)&x_img[b * HW + gy1 * WW + xe];
                __sincosf(fmaf(2.0f * PIf, v.x, -PIf), &sE1, &cE1);
                __sincosf(fmaf(2.0f * PIf, v.y, -PIf), &sO1, &cO1);
            }
        } else {
            if (in0) {
                float2 vs = *(const float2*)&g_s[b * HW + gy0 * WW + xe];
                float2 vc = *(const float2*)&g_c[b * HW + gy0 * WW + xe];
                sE0 = vs.x; sO0 = vs.y; cE0 = vc.x; cO0 = vc.y;
            }
            if (in1) {
                float2 vs = *(const float2*)&g_s[b * HW + gy1 * WW + xe];
                float2 vc = *(const float2*)&g_c[b * HW + gy1 * WW + xe];
                sE1 = vs.x; sO1 = vs.y; cE1 = vc.x; cO1 = vc.y;
            }
        }
        bufA[rp * RS + iE] = make_ulonglong2(pk2(sE0, sE1), pk2(cE0, cE1));
        bufA[rp * RS + iO] = make_ulonglong2(pk2(sO0, sO1), pk2(cO0, cO1));
    }
    __syncthreads();

    // 5 fused steps, ping-pong A<->B, software-pipelined loads.
    const ulonglong2* p = bufA;
    ulonglong2* q = bufB;
#pragma unroll
    for (int st = 0; st < HALO; st++) {
        int base = r0p * RS;
        ulonglong2 pE = p[base - RS + iE];
        ulonglong2 pO = p[base - RS + iO];
        ulonglong2 cE = p[base + iE];
        ulonglong2 cO = p[base + iO];
        u64 uEs = add2(pE.x, cE.x), uEc = add2(pE.y, cE.y);
        u64 uOs = add2(pO.x, cO.x), uOc = add2(pO.y, cO.y);
        // Prologue loads for iter 0.
        ulonglong2 nE = p[base + RS + iE];
        ulonglong2 nO = p[base + RS + iO];
        ulonglong2 lf = p[base + iL];
        ulonglong2 rg = p[base + iR];
#pragma unroll
        for (int j = 0; j < PACKS_PER; j++) {
            // Prefetch next iteration's loads before this iteration's compute.
            ulonglong2 lf2, rg2, nE2, nO2;
            if (j < PACKS_PER - 1) {
                lf2 = p[base + RS + iL];
                rg2 = p[base + RS + iR];
                nE2 = p[base + 2 * RS + iE];
                nO2 = p[base + 2 * RS + iO];
            }

            u64 vEs = add2(cE.x, nE.x), vEc = add2(cE.y, nE.y);
            u64 vOs = add2(cO.x, nO.x), vOc = add2(cO.y, nO.y);

            // Even col: left = lf (col 2t-1), right = cO (col 2t+1, registers)
            ulonglong2 oE = upd(cE, uEs, uEc, vEs, vEc, lf, cO, dtoE[j], C);
            // Odd col: left = cE (col 2t, registers), right = rg (col 2t+2)
            ulonglong2 oO = upd(cO, uOs, uOc, vOs, vOc, cE, rg, dtoO[j], C);

            q[base + iE] = oE;
            q[base + iO] = oO;

            uEs = vEs; uEc = vEc; uOs = vOs; uOc = vOc;
            cE = nE; cO = nO;
            nE = nE2; nO = nO2; lf = lf2; rg = rg2;
            base += RS;
        }
        __syncthreads();
        const ulonglong2* tp = q;
        q = (ulonglong2*)p;
        p = tp;
    }
    // Result now in p.

    // Write back interior rows (tile rows HALO..HALO+TY-1).
#pragma unroll
    for (int j = 0; j < PACKS_PER; j++) {
        const int rp = r0p + j;
        ulonglong2 vE = p[rp * RS + iE];
        ulonglong2 vO = p[rp * RS + iO];
        float sE0, sE1, cE0, cE1, sO0, sO1, cO0, cO1;
        unpk2(vE.x, sE0, sE1);
        unpk2(vE.y, cE0, cE1);
        unpk2(vO.x, sO0, sO1);
        unpk2(vO.y, cO0, cO1);
        const int rt0 = 2 * (rp - 1);
#pragma unroll
        for (int par = 0; par < 2; par++) {
            const int rt = rt0 + par;
            if (rt >= HALO && rt < HALO + TY) {
                const int gy = y0 + (rt - HALO);
                if (gy < HH) {
                    float s0 = par ? sE1 : sE0;
                    float s1 = par ? sO1 : sO0;
                    float c0 = par ? cE1 : cE0;
                    float c1 = par ? cO1 : cO0;
                    if (PHASE == 0) {
                        *(float2*)&g_s[b * HW + gy * WW + xe] = make_float2(s0, s1);
                        *(float2*)&g_c[b * HW + gy * WW + xe] = make_float2(c0, c1);
                    } else {
                        const int pix = gy * WW + xe;
                        *(float2*)&out[(long)b * (2 * HW) + pix] = make_float2(c0, c1);
                        *(float2*)&out[(long)b * (2 * HW) + HW + pix] = make_float2(s0, s1);
                    }
                }
            }
        }
    }
}

extern "C" void kernel_launch(void* const* d_in, const int* in_sizes, int n_in,
                              void* d_out, int out_size) {
    const float* x_img = (const float*)d_in[0];  // (B,1,H,W)
    const float* omega = (const float*)d_in[1];  // (1,1,H,W)
    const float* Kp    = (const float*)d_in[2];  // scalar
    float* out = (float*)d_out;

    static bool configured = false;
    if (!configured) {
        cudaFuncSetAttribute(fused5_kernel<0>,
                             cudaFuncAttributeMaxDynamicSharedMemorySize, SMEM_BYTES);
        cudaFuncSetAttribute(fused5_kernel<1>,
                             cudaFuncAttributeMaxDynamicSharedMemorySize, SMEM_BYTES);
        configured = true;
    }

    dim3 grid(TILES, BB);
    dim3 block(NTHREADS);
    fused5_kernel<0><<<grid, block, SMEM_BYTES>>>(x_img, omega, Kp, out);
    fused5_kernel<1><<<grid, block, SMEM_BYTES>>>(x_img, omega, Kp, out);
}

// round 8
// speedup vs baseline: 1.6086x; 1.3721x over previous
#include <cuda_runtime.h>

#define HH 224
#define WW 224
#define HW (HH * WW)
#define BB 256
#define NTOT (BB * HW)
#define DTc 0.15f
#define PIf 3.14159265358979f

#define TY 46                  // interior rows per tile
#define HALO 5                 // 5 fused steps per kernel
#define RR (TY + 2 * HALO)     // 56 data rows
#define RPAIRS (RR / 2)        // 28 vertical row-pair packs
#define RPP (RPAIRS + 2)       // +2 zero-pad pack rows -> 30
#define TCOLS 112              // thread-columns (each owns 2 pixel cols)
#define PW2 114                // plane width incl pads
#define RS (2 * PW2)           // row stride: E plane then O plane (228 cells)
#define TILES 5
#define STRIPS 4
#define NTHREADS (TCOLS * STRIPS)    // 448; 2 CTAs/SM -> 73 regs budget
#define PACKS_PER (RPAIRS / STRIPS)  // 7
#define SMP (RPP * RS)               // cells per buffer = 6840
#define SMEM_BYTES (2 * SMP * 8)     // fp16 cells: 109440 B -> 2 CTAs/SM

typedef unsigned long long u64;
typedef unsigned int u32;

__device__ float g_s[NTOT];
__device__ float g_c[NTOT];
__device__ int g_flag;          // omega-nonzero flag (recomputed every launch)

// ---- packed f32x2 helpers ----
__device__ __forceinline__ u64 pk2(float lo, float hi) {
    u64 r; asm("mov.b64 %0, {%1, %2};" : "=l"(r) : "f"(lo), "f"(hi)); return r;
}
__device__ __forceinline__ void unpk2(u64 v, float& lo, float& hi) {
    asm("mov.b64 {%0, %1}, %2;" : "=f"(lo), "=f"(hi) : "l"(v));
}
__device__ __forceinline__ u64 add2(u64 a, u64 b) {
    u64 d; asm("add.rn.f32x2 %0, %1, %2;" : "=l"(d) : "l"(a), "l"(b)); return d;
}
__device__ __forceinline__ u64 mul2(u64 a, u64 b) {
    u64 d; asm("mul.rn.f32x2 %0, %1, %2;" : "=l"(d) : "l"(a), "l"(b)); return d;
}
__device__ __forceinline__ u64 fma2(u64 a, u64 b, u64 c) {
    u64 d; asm("fma.rn.f32x2 %0, %1, %2, %3;" : "=l"(d) : "l"(a), "l"(b), "l"(c)); return d;
}
__device__ __forceinline__ u64 neg2(u64 a) { return a ^ 0x8000000080000000ULL; }

// ---- fp16x2 helpers ----
__device__ __forceinline__ u32 hadd2(u32 a, u32 b) {
    u32 d; asm("add.rn.f16x2 %0, %1, %2;" : "=r"(d) : "r"(a), "r"(b)); return d;
}
// (a.hi16, b.lo16)
__device__ __forceinline__ u32 funnel16(u32 a, u32 b) {
    u32 d; asm("prmt.b32 %0, %1, %2, 0x5432;" : "=r"(d) : "r"(a), "r"(b)); return d;
}
__device__ __forceinline__ u64 h2f(u32 h) {
    float lo, hi;
    asm("{\n\t.reg .b16 l, h;\n\tmov.b32 {l, h}, %2;\n\t"
        "cvt.f32.f16 %0, l;\n\tcvt.f32.f16 %1, h;\n\t}"
        : "=f"(lo), "=f"(hi) : "r"(h));
    return pk2(lo, hi);
}
__device__ __forceinline__ u32 fpair2h(float lo, float hi) {
    u32 d; asm("cvt.rn.f16x2.f32 %0, %1, %2;" : "=r"(d) : "f"(hi), "f"(lo)); return d;
}
__device__ __forceinline__ u32 f2h(u64 v) {
    float lo, hi; unpk2(v, lo, hi); return fpair2h(lo, hi);
}

struct SC { u64 DTK2, ONE2, C3, C5, C2, C4; };

// Rotation core: inputs fp32x2 (cur sin/cos), half2 neighbor sums, dto addend.
__device__ __forceinline__ void rot_core(u64 fs, u64 fc, u32 snh, u32 cnh,
                                         u64 dto, const SC& C,
                                         u64& os, u64& oc) {
    u64 sn = h2f(snh), cn = h2f(cnh);
    u64 m = neg2(fs);
    u64 coup = fma2(fc, sn, mul2(m, cn));
    u64 d = fma2(C.DTK2, coup, dto);
    u64 d2 = mul2(d, d);
    u64 sd = mul2(d, fma2(d2, fma2(d2, C.C5, C.C3), C.ONE2));
    u64 cd = fma2(d2, fma2(d2, C.C4, C.C2), C.ONE2);
    os = fma2(fs, cd, mul2(fc, sd));
    oc = fma2(fc, cd, mul2(m, sd));
}

__global__ void __launch_bounds__(1024) flag_kernel(const float* __restrict__ om) {
    int acc = 0;
    for (int i = threadIdx.x; i < HW; i += 1024) acc |= (om[i] != 0.0f);
    int any = __syncthreads_or(acc);
    if (threadIdx.x == 0) g_flag = any;
}

template <int PHASE>  // 0: x_img -> g_s/g_c ; 1: g_s/g_c -> out
__global__ void __launch_bounds__(NTHREADS, 2)
fused5_kernel(const float* __restrict__ x_img,
              const float* __restrict__ omega,
              const float* __restrict__ Kp,
              float* __restrict__ out) {
    extern __shared__ uint2 sm2[];
    uint2* bufA = sm2;
    uint2* bufB = sm2 + SMP;

    const int tid = threadIdx.x;
    const int t = tid % TCOLS;         // owns pixel cols 2t, 2t+1
    const int strip = tid / TCOLS;
    const int r0p = 1 + strip * PACKS_PER;
    const int b = blockIdx.y;
    const int y0 = blockIdx.x * TY;
    const int xe = 2 * t;
    const int flg = g_flag;
    const float2* __restrict__ om2 = (const float2*)omega;

    const float DTK = DTc * Kp[0];
    SC C;
    C.DTK2 = pk2(DTK, DTK);
    C.ONE2 = pk2(1.0f, 1.0f);
    C.C3 = pk2(-1.0f / 6.0f, -1.0f / 6.0f);
    C.C5 = pk2(8.3333333e-3f, 8.3333333e-3f);
    C.C2 = pk2(-0.5f, -0.5f);
    C.C4 = pk2(4.1666668e-2f, 4.1666668e-2f);

    const int iE = t + 1;              // own even col
    const int iO = PW2 + t + 1;        // own odd col
    const int iL = PW2 + t;            // left neighbor (odd plane)
    const int iR = t + 2;              // right neighbor (even plane)

    // Zero pad ring of both buffers (h2 zero bits = 0.0).
    const uint2 Z = make_uint2(0u, 0u);
    for (int i = tid; i < RS; i += NTHREADS) {
        bufA[i] = Z; bufA[(RPP - 1) * RS + i] = Z;
        bufB[i] = Z; bufB[(RPP - 1) * RS + i] = Z;
    }
    for (int r = 1 + tid; r < RPP - 1; r += NTHREADS) {
        bufA[r * RS + 113] = Z; bufA[r * RS + 114] = Z;
        bufB[r * RS + 113] = Z; bufB[r * RS + 114] = Z;
    }

    // Init state into bufA (fp16 cells); out-of-image rows = exact 0.
#pragma unroll
    for (int j = 0; j < PACKS_PER; j++) {
        const int rp = r0p + j;
        const int gy0 = y0 - HALO + 2 * (rp - 1);
        const int gy1 = gy0 + 1;
        const bool in0 = (gy0 >= 0) && (gy0 < HH);
        const bool in1 = (gy1 >= 0) && (gy1 < HH);
        float sE0 = 0.f, cE0 = 0.f, sO0 = 0.f, cO0 = 0.f;
        float sE1 = 0.f, cE1 = 0.f, sO1 = 0.f, cO1 = 0.f;
        if (PHASE == 0) {
            if (in0) {
                float2 v = *(const float2*)&x_img[b * HW + gy0 * WW + xe];
                __sincosf(fmaf(2.0f * PIf, v.x, -PIf), &sE0, &cE0);
                __sincosf(fmaf(2.0f * PIf, v.y, -PIf), &sO0, &cO0);
            }
            if (in1) {
                float2 v = *(const float2*)&x_img[b * HW + gy1 * WW + xe];
                __sincosf(fmaf(2.0f * PIf, v.x, -PIf), &sE1, &cE1);
                __sincosf(fmaf(2.0f * PIf, v.y, -PIf), &sO1, &cO1);
            }
        } else {
            if (in0) {
                float2 vs = *(const float2*)&g_s[b * HW + gy0 * WW + xe];
                float2 vc = *(const float2*)&g_c[b * HW + gy0 * WW + xe];
                sE0 = vs.x; sO0 = vs.y; cE0 = vc.x; cO0 = vc.y;
            }
            if (in1) {
                float2 vs = *(const float2*)&g_s[b * HW + gy1 * WW + xe];
                float2 vc = *(const float2*)&g_c[b * HW + gy1 * WW + xe];
                sE1 = vs.x; sO1 = vs.y; cE1 = vc.x; cO1 = vc.y;
            }
        }
        bufA[rp * RS + iE] = make_uint2(fpair2h(sE0, sE1), fpair2h(cE0, cE1));
        bufA[rp * RS + iO] = make_uint2(fpair2h(sO0, sO1), fpair2h(cO0, cO1));
    }
    __syncthreads();

    const int gybase = y0 - HALO + 2 * (r0p - 1);
    const uint2* p = bufA;
    uint2* q = bufB;

    // Steps 1..HALO-1: smem -> smem (fp16). Runtime loop (small I$ footprint).
#pragma unroll 1
    for (int st = 0; st < HALO - 1; st++) {
        int base = r0p * RS;
        uint2 pE = p[base - RS + iE], pO = p[base - RS + iO];
        uint2 cE = p[base + iE], cO = p[base + iO];
        u32 uEs = hadd2(pE.x, cE.x), uEc = hadd2(pE.y, cE.y);
        u32 uOs = hadd2(pO.x, cO.x), uOc = hadd2(pO.y, cO.y);
        u64 fEs = h2f(cE.x), fEc = h2f(cE.y);
        u64 fOs = h2f(cO.x), fOc = h2f(cO.y);
#pragma unroll
        for (int j = 0; j < PACKS_PER; j++) {
            uint2 nE = p[base + RS + iE];
            uint2 nO = p[base + RS + iO];
            uint2 lf = p[base + iL];
            uint2 rg = p[base + iR];

            u32 vEs = hadd2(cE.x, nE.x), vEc = hadd2(cE.y, nE.y);
            u32 vOs = hadd2(cO.x, nO.x), vOc = hadd2(cO.y, nO.y);
            u32 snE = hadd2(funnel16(uEs, vEs), hadd2(lf.x, cO.x));
            u32 cnE = hadd2(funnel16(uEc, vEc), hadd2(lf.y, cO.y));
            u32 snO = hadd2(funnel16(uOs, vOs), hadd2(cE.x, rg.x));
            u32 cnO = hadd2(funnel16(uOc, vOc), hadd2(cE.y, rg.y));

            u64 dtoE = 0, dtoO = 0;
            if (flg) {   // uniform branch; omega==0 in fast path
                const int gy0 = gybase + 2 * j, gy1 = gy0 + 1;
                float2 o0 = (gy0 >= 0 && gy0 < HH) ? om2[gy0 * TCOLS + t] : make_float2(0.f, 0.f);
                float2 o1 = (gy1 >= 0 && gy1 < HH) ? om2[gy1 * TCOLS + t] : make_float2(0.f, 0.f);
                dtoE = pk2(DTc * o0.x, DTc * o1.x);
                dtoO = pk2(DTc * o0.y, DTc * o1.y);
            }

            u64 os, oc;
            rot_core(fEs, fEc, snE, cnE, dtoE, C, os, oc);
            q[base + iE] = make_uint2(f2h(os), f2h(oc));
            rot_core(fOs, fOc, snO, cnO, dtoO, C, os, oc);
            q[base + iO] = make_uint2(f2h(os), f2h(oc));

            uEs = vEs; uEc = vEc; uOs = vOs; uOc = vOc;
            cE = nE; cO = nO;
            fEs = h2f(nE.x); fEc = h2f(nE.y);
            fOs = h2f(nO.x); fOc = h2f(nO.y);
            base += RS;
        }
        __syncthreads();
        const uint2* tp = q;
        q = (uint2*)p;
        p = tp;
    }

    // Final step: compute in fp32 and write DIRECTLY to global (no fp16 quantize).
    {
        int base = r0p * RS;
        uint2 pE = p[base - RS + iE], pO = p[base - RS + iO];
        uint2 cE = p[base + iE], cO = p[base + iO];
        u32 uEs = hadd2(pE.x, cE.x), uEc = hadd2(pE.y, cE.y);
        u32 uOs = hadd2(pO.x, cO.x), uOc = hadd2(pO.y, cO.y);
        u64 fEs = h2f(cE.x), fEc = h2f(cE.y);
        u64 fOs = h2f(cO.x), fOc = h2f(cO.y);
#pragma unroll
        for (int j = 0; j < PACKS_PER; j++) {
            uint2 nE = p[base + RS + iE];
            uint2 nO = p[base + RS + iO];
            uint2 lf = p[base + iL];
            uint2 rg = p[base + iR];

            u32 vEs = hadd2(cE.x, nE.x), vEc = hadd2(cE.y, nE.y);
            u32 vOs = hadd2(cO.x, nO.x), vOc = hadd2(cO.y, nO.y);
            u32 snE = hadd2(funnel16(uEs, vEs), hadd2(lf.x, cO.x));
            u32 cnE = hadd2(funnel16(uEc, vEc), hadd2(lf.y, cO.y));
            u32 snO = hadd2(funnel16(uOs, vOs), hadd2(cE.x, rg.x));
            u32 cnO = hadd2(funnel16(uOc, vOc), hadd2(cE.y, rg.y));

            u64 dtoE = 0, dtoO = 0;
            if (flg) {
                const int gy0 = gybase + 2 * j, gy1 = gy0 + 1;
                float2 o0 = (gy0 >= 0 && gy0 < HH) ? om2[gy0 * TCOLS + t] : make_float2(0.f, 0.f);
                float2 o1 = (gy1 >= 0 && gy1 < HH) ? om2[gy1 * TCOLS + t] : make_float2(0.f, 0.f);
                dtoE = pk2(DTc * o0.x, DTc * o1.x);
                dtoO = pk2(DTc * o0.y, DTc * o1.y);
            }

            u64 osE, ocE, osO, ocO;
            rot_core(fEs, fEc, snE, cnE, dtoE, C, osE, ocE);
            rot_core(fOs, fOc, snO, cnO, dtoO, C, osO, ocO);

            float sE0, sE1, cc0, cc1, sO0, sO1, cO0v, cO1v;
            unpk2(osE, sE0, sE1); unpk2(ocE, cc0, cc1);
            unpk2(osO, sO0, sO1); unpk2(ocO, cO0v, cO1v);
            const int rt0 = 2 * (r0p + j - 1);
#pragma unroll
            for (int par = 0; par < 2; par++) {
                const int rt = rt0 + par;
                if (rt >= HALO && rt < HALO + TY) {
                    const int gy = y0 + (rt - HALO);
                    if (gy < HH) {
                        float ws0 = par ? sE1 : sE0;
                        float ws1 = par ? sO1 : sO0;
                        float wc0 = par ? cc1 : cc0;
                        float wc1 = par ? cO1v : cO0v;
                        if (PHASE == 0) {
                            *(float2*)&g_s[b * HW + gy * WW + xe] = make_float2(ws0, ws1);
                            *(float2*)&g_c[b * HW + gy * WW + xe] = make_float2(wc0, wc1);
                        } else {
                            const int pix = gy * WW + xe;
                            *(float2*)&out[(long)b * (2 * HW) + pix] = make_float2(wc0, wc1);
                            *(float2*)&out[(long)b * (2 * HW) + HW + pix] = make_float2(ws0, ws1);
                        }
                    }
                }
            }

            uEs = vEs; uEc = vEc; uOs = vOs; uOc = vOc;
            cE = nE; cO = nO;
            fEs = h2f(nE.x); fEc = h2f(nE.y);
            fOs = h2f(nO.x); fOc = h2f(nO.y);
            base += RS;
        }
    }
}

extern "C" void kernel_launch(void* const* d_in, const int* in_sizes, int n_in,
                              void* d_out, int out_size) {
    const float* x_img = (const float*)d_in[0];  // (B,1,H,W)
    const float* omega = (const float*)d_in[1];  // (1,1,H,W)
    const float* Kp    = (const float*)d_in[2];  // scalar
    float* out = (float*)d_out;

    static bool configured = false;
    if (!configured) {
        cudaFuncSetAttribute(fused5_kernel<0>,
                             cudaFuncAttributeMaxDynamicSharedMemorySize, SMEM_BYTES);
        cudaFuncSetAttribute(fused5_kernel<1>,
                             cudaFuncAttributeMaxDynamicSharedMemorySize, SMEM_BYTES);
        configured = true;
    }

    flag_kernel<<<1, 1024>>>(omega);

    dim3 grid(TILES, BB);
    dim3 block(NTHREADS);
    fused5_kernel<0><<<grid, block, SMEM_BYTES>>>(x_img, omega, Kp, out);
    fused5_kernel<1><<<grid, block, SMEM_BYTES>>>(x_img, omega, Kp, out);
}